// round 1
// baseline (speedup 1.0000x reference)
#include <cuda_runtime.h>
#include <math.h>

#define NN 100000
#define NE 1600000
#define NC 40
#define CJ 10              // 40 floats = 10 float4 chunks
#define NT 50000
#define NC4 (NN*CJ)
#define SCAN_T 1024
#define SCAN_B ((NN + SCAN_T - 1)/SCAN_T)

#define ALPHA_C 0.979f
#define ALPHA_S 0.756f

// ---- scratch (static device globals: allocation-free) ----
static __device__ int    g_deg[NN];
static __device__ int    g_rowptr[NN+1];
static __device__ int    g_cursor[NN];
static __device__ int    g_colidx[NE];
static __device__ float  g_norm[NN];
static __device__ float  g_scalebuf[NN];
static __device__ float4 g_h0[NC4];
static __device__ float4 g_h1[NC4];
static __device__ float4 g_y[NC4];      // holds error rows, then smoothed_error
static __device__ float4 g_base[NC4];   // (1-alpha)*y0 term
static __device__ int    g_bsum[SCAN_B];
static __device__ double g_sigma;

__global__ void k_init() {
    int v = blockIdx.x*blockDim.x + threadIdx.x;
    if (v < NN) g_deg[v] = 0;
    if (v == 0) g_sigma = 0.0;
}

__global__ void k_count(const int* __restrict__ dst) {
    int e = blockIdx.x*blockDim.x + threadIdx.x;
    if (e < NE) atomicAdd(&g_deg[dst[e]], 1);
}

__global__ void k_scan1() {
    __shared__ int sh[32];
    int v = blockIdx.x*SCAN_T + threadIdx.x;
    int d = (v < NN) ? g_deg[v] : 0;
    int s = d;
    #pragma unroll
    for (int o = 16; o; o >>= 1) s += __shfl_down_sync(0xffffffffu, s, o);
    if ((threadIdx.x & 31) == 0) sh[threadIdx.x >> 5] = s;
    __syncthreads();
    if (threadIdx.x < 32) {
        int t = sh[threadIdx.x];
        #pragma unroll
        for (int o = 16; o; o >>= 1) t += __shfl_down_sync(0xffffffffu, t, o);
        if (threadIdx.x == 0) g_bsum[blockIdx.x] = t;
    }
}

__global__ void k_scan2() {
    if (threadIdx.x == 0) {
        int r = 0;
        for (int b = 0; b < SCAN_B; b++) { int t = g_bsum[b]; g_bsum[b] = r; r += t; }
    }
}

__global__ void k_scan3() {
    __shared__ int wsum[32];
    int v = blockIdx.x*SCAN_T + threadIdx.x;
    int d = (v < NN) ? g_deg[v] : 0;
    int lane = threadIdx.x & 31, w = threadIdx.x >> 5;
    int inc = d;
    #pragma unroll
    for (int o = 1; o < 32; o <<= 1) {
        int t = __shfl_up_sync(0xffffffffu, inc, o);
        if (lane >= o) inc += t;
    }
    if (lane == 31) wsum[w] = inc;
    __syncthreads();
    if (w == 0) {
        int t = wsum[lane];
        int ti = t;
        #pragma unroll
        for (int o = 1; o < 32; o <<= 1) {
            int x = __shfl_up_sync(0xffffffffu, ti, o);
            if (lane >= o) ti += x;
        }
        wsum[lane] = ti - t;   // exclusive
    }
    __syncthreads();
    int ex = inc - d + wsum[w] + g_bsum[blockIdx.x];
    if (v < NN) {
        g_rowptr[v] = ex;
        g_cursor[v] = ex;
        g_norm[v] = 1.0f / sqrtf((float)(d > 0 ? d : 1));
        if (v == NN-1) g_rowptr[NN] = ex + d;
    }
}

__global__ void k_fill(const int* __restrict__ src, const int* __restrict__ dst) {
    int e = blockIdx.x*blockDim.x + threadIdx.x;
    if (e < NE) {
        int p = atomicAdd(&g_cursor[dst[e]], 1);
        g_colidx[p] = src[e];
    }
}

__global__ void k_zero2() {
    int g = blockIdx.x*blockDim.x + threadIdx.x;
    if (g < NC4) {
        float4 z = make_float4(0.f, 0.f, 0.f, 0.f);
        g_h0[g] = z;
        g_base[g] = z;
    }
}

// error[mask] = onehot(y_true) - y_soft[mask]; last occurrence wins (mask sorted)
__global__ void k_scatter1(const float* __restrict__ y_soft,
                           const int* __restrict__ mask,
                           const int* __restrict__ y_true) {
    int g = blockIdx.x*blockDim.x + threadIdx.x;
    if (g >= NT*NC) return;
    int i = g / NC, c = g - NC*i;
    int m = mask[i];
    bool last = (i == NT-1) || (mask[i+1] != m);
    if (last) {
        float err = ((c == y_true[i]) ? 1.0f : 0.0f) - y_soft[m*NC + c];
        ((float*)g_h0)[m*NC + c]   = err * g_norm[m];       // pre-scaled h
        ((float*)g_base)[m*NC + c] = (1.0f - ALPHA_C) * err;
        ((float*)g_y)[m*NC + c]    = err;                   // raw error for sigma
    }
}

// sigma = sum_i sum_c |error[mask[i]][c]|  (duplicates count repeatedly)
__global__ void k_sigma(const int* __restrict__ mask) {
    __shared__ float sh[256];
    int g = blockIdx.x*256 + threadIdx.x;
    float val = 0.f;
    if (g < NT*NC) {
        int i = g / NC, c = g - NC*i;
        int m = mask[i];
        val = fabsf(((const float*)g_y)[m*NC + c]);
    }
    sh[threadIdx.x] = val;
    __syncthreads();
    for (int o = 128; o; o >>= 1) {
        if (threadIdx.x < o) sh[threadIdx.x] += sh[threadIdx.x + o];
        __syncthreads();
    }
    if (threadIdx.x == 0) atomicAdd(&g_sigma, (double)sh[0]);
}

// one propagation layer: y_new = clamp(base + alpha*norm_v * sum_{u->v} h_u)
// writes h_new = y_new*norm_v (for next layer) and/or y_new
__global__ void k_prop(const float4* __restrict__ hin,
                       float4* __restrict__ hout,
                       float4* __restrict__ yout,
                       float alpha, float lo, float hi) {
    int g = blockIdx.x*blockDim.x + threadIdx.x;
    if (g >= NC4) return;
    int v = g / CJ;
    int j = g - v*CJ;
    int s = __ldg(&g_rowptr[v]);
    int e = __ldg(&g_rowptr[v+1]);
    float4 acc = make_float4(0.f, 0.f, 0.f, 0.f);
    #pragma unroll 4
    for (int k = s; k < e; k++) {
        int u = __ldg(&g_colidx[k]);
        float4 t = __ldg(&hin[u*CJ + j]);
        acc.x += t.x; acc.y += t.y; acc.z += t.z; acc.w += t.w;
    }
    float nv = g_norm[v];
    float a = alpha * nv;
    float4 b = g_base[g];
    float4 y;
    y.x = fminf(fmaxf(fmaf(a, acc.x, b.x), lo), hi);
    y.y = fminf(fmaxf(fmaf(a, acc.y, b.y), lo), hi);
    y.z = fminf(fmaxf(fmaf(a, acc.z, b.z), lo), hi);
    y.w = fminf(fmaxf(fmaf(a, acc.w, b.w), lo), hi);
    if (yout) yout[g] = y;
    if (hout) {
        float4 h;
        h.x = y.x*nv; h.y = y.y*nv; h.z = y.z*nv; h.w = y.w*nv;
        hout[g] = h;
    }
}

__global__ void k_scale() {
    int v = blockIdx.x*blockDim.x + threadIdx.x;
    if (v >= NN) return;
    float denom = 0.f;
    #pragma unroll
    for (int j = 0; j < CJ; j++) {
        float4 t = g_y[v*CJ + j];
        denom += fabsf(t.x) + fabsf(t.y) + fabsf(t.z) + fabsf(t.w);
    }
    float sig = (float)g_sigma / (float)NT;
    float s = sig / denom;
    if (isinf(s) || s > 1000.0f) s = 1.0f;
    g_scalebuf[v] = s;
}

// y1 = y_soft + scale*smoothed_error; emit h = y1*norm and base = (1-as)*y1
__global__ void k_apply(const float4* __restrict__ y_soft) {
    int g = blockIdx.x*blockDim.x + threadIdx.x;
    if (g >= NC4) return;
    int v = g / CJ;
    float s = g_scalebuf[v];
    float nv = g_norm[v];
    float4 se = g_y[g];
    float4 ys = y_soft[g];
    float4 y1;
    y1.x = fmaf(s, se.x, ys.x);
    y1.y = fmaf(s, se.y, ys.y);
    y1.z = fmaf(s, se.z, ys.z);
    y1.w = fmaf(s, se.w, ys.w);
    float4 h;
    h.x = y1.x*nv; h.y = y1.y*nv; h.z = y1.z*nv; h.w = y1.w*nv;
    g_h0[g] = h;
    float4 b;
    const float oma = 1.0f - ALPHA_S;
    b.x = oma*y1.x; b.y = oma*y1.y; b.z = oma*y1.z; b.w = oma*y1.w;
    g_base[g] = b;
}

// y1[mask] = onehot(y_true), last occurrence wins; update h and base rows
__global__ void k_scatter2(const int* __restrict__ mask,
                           const int* __restrict__ y_true) {
    int g = blockIdx.x*blockDim.x + threadIdx.x;
    if (g >= NT*NC) return;
    int i = g / NC, c = g - NC*i;
    int m = mask[i];
    bool last = (i == NT-1) || (mask[i+1] != m);
    if (last) {
        float val = (c == y_true[i]) ? 1.0f : 0.0f;
        ((float*)g_h0)[m*NC + c]   = val * g_norm[m];
        ((float*)g_base)[m*NC + c] = (1.0f - ALPHA_S) * val;
    }
}

extern "C" void kernel_launch(void* const* d_in, const int* in_sizes, int n_in,
                              void* d_out, int out_size) {
    const float4* y_soft = (const float4*)d_in[0];
    const float*  y_soft_f = (const float*)d_in[0];
    const int* src    = (const int*)d_in[1];
    const int* dst    = (const int*)d_in[2];
    const int* y_true = (const int*)d_in[3];
    const int* mask   = (const int*)d_in[4];

    float4 *h0, *h1, *yb;
    cudaGetSymbolAddress((void**)&h0, g_h0);
    cudaGetSymbolAddress((void**)&h1, g_h1);
    cudaGetSymbolAddress((void**)&yb, g_y);

    const int B = 256;
    const int GN  = (NN + B - 1) / B;
    const int GE  = (NE + B - 1) / B;
    const int G4  = (NC4 + B - 1) / B;
    const int GTC = (NT*NC + B - 1) / B;

    // ---- build CSR + norm ----
    k_init<<<GN, B>>>();
    k_count<<<GE, B>>>(dst);
    k_scan1<<<SCAN_B, SCAN_T>>>();
    k_scan2<<<1, 32>>>();
    k_scan3<<<SCAN_B, SCAN_T>>>();
    k_fill<<<GE, B>>>(src, dst);

    // ---- correct phase ----
    k_zero2<<<G4, B>>>();
    k_scatter1<<<GTC, B>>>(y_soft_f, mask, y_true);
    k_sigma<<<GTC, B>>>(mask);
    for (int i = 0; i < 9; i++)
        k_prop<<<G4, B>>>((i & 1) ? h1 : h0, (i & 1) ? h0 : h1, nullptr,
                          ALPHA_C, -1.0f, 1.0f);
    k_prop<<<G4, B>>>(h1, nullptr, yb, ALPHA_C, -1.0f, 1.0f);  // smoothed_error -> g_y

    // ---- scale + apply + re-mask ----
    k_scale<<<GN, B>>>();
    k_apply<<<G4, B>>>(y_soft);
    k_scatter2<<<GTC, B>>>(mask, y_true);

    // ---- smooth phase ----
    for (int i = 0; i < 9; i++)
        k_prop<<<G4, B>>>((i & 1) ? h1 : h0, (i & 1) ? h0 : h1, nullptr,
                          ALPHA_S, 0.0f, 1.0f);
    k_prop<<<G4, B>>>(h1, nullptr, (float4*)d_out, ALPHA_S, 0.0f, 1.0f);
}

// round 4
// speedup vs baseline: 1.2224x; 1.2224x over previous
#include <cuda_runtime.h>
#include <cuda_fp16.h>
#include <math.h>

#define NN 100000
#define NE 1600000
#define NC 40
#define CJ 10              // 40 floats = 10 float4 chunks (fp32 buffers)
#define HJ 5               // 40 halves = 5 uint4 chunks (fp16 h buffer)
#define NT 50000
#define NC4 (NN*CJ)
#define NH4 (NN*HJ)
#define SCAN_T 1024
#define SCAN_B ((NN + SCAN_T - 1)/SCAN_T)

#define ALPHA_C 0.979f
#define ALPHA_S 0.756f

// ---- scratch (static device globals: allocation-free) ----
static __device__ int    g_deg[NN];
static __device__ int    g_rowptr[NN+1];
static __device__ int    g_cursor[NN];
static __device__ int    g_colidx[NE];
static __device__ float  g_norm[NN];
static __device__ float  g_scalebuf[NN];
static __device__ uint4  g_h0[NH4];     // fp16 feature buffer (ping)
static __device__ uint4  g_h1[NH4];     // fp16 feature buffer (pong)
static __device__ float4 g_y[NC4];      // holds raw error, then smoothed_error (fp32)
static __device__ float4 g_base[NC4];   // (1-alpha)*y0 term (fp32)
static __device__ int    g_bsum[SCAN_B];
static __device__ double g_sigma;

__global__ void k_init() {
    int v = blockIdx.x*blockDim.x + threadIdx.x;
    if (v < NN) g_deg[v] = 0;
    if (v == 0) g_sigma = 0.0;
}

__global__ void k_count(const int* __restrict__ dst) {
    int e = blockIdx.x*blockDim.x + threadIdx.x;
    if (e < NE) atomicAdd(&g_deg[dst[e]], 1);
}

__global__ void k_scan1() {
    __shared__ int sh[32];
    int v = blockIdx.x*SCAN_T + threadIdx.x;
    int d = (v < NN) ? g_deg[v] : 0;
    int s = d;
    #pragma unroll
    for (int o = 16; o; o >>= 1) s += __shfl_down_sync(0xffffffffu, s, o);
    if ((threadIdx.x & 31) == 0) sh[threadIdx.x >> 5] = s;
    __syncthreads();
    if (threadIdx.x < 32) {
        int t = sh[threadIdx.x];
        #pragma unroll
        for (int o = 16; o; o >>= 1) t += __shfl_down_sync(0xffffffffu, t, o);
        if (threadIdx.x == 0) g_bsum[blockIdx.x] = t;
    }
}

__global__ void k_scan2() {
    if (threadIdx.x == 0) {
        int r = 0;
        for (int b = 0; b < SCAN_B; b++) { int t = g_bsum[b]; g_bsum[b] = r; r += t; }
    }
}

__global__ void k_scan3() {
    __shared__ int wsum[32];
    int v = blockIdx.x*SCAN_T + threadIdx.x;
    int d = (v < NN) ? g_deg[v] : 0;
    int lane = threadIdx.x & 31, w = threadIdx.x >> 5;
    int inc = d;
    #pragma unroll
    for (int o = 1; o < 32; o <<= 1) {
        int t = __shfl_up_sync(0xffffffffu, inc, o);
        if (lane >= o) inc += t;
    }
    if (lane == 31) wsum[w] = inc;
    __syncthreads();
    if (w == 0) {
        int t = wsum[lane];
        int ti = t;
        #pragma unroll
        for (int o = 1; o < 32; o <<= 1) {
            int x = __shfl_up_sync(0xffffffffu, ti, o);
            if (lane >= o) ti += x;
        }
        wsum[lane] = ti - t;   // exclusive
    }
    __syncthreads();
    int ex = inc - d + wsum[w] + g_bsum[blockIdx.x];
    if (v < NN) {
        g_rowptr[v] = ex;
        g_cursor[v] = ex;
        g_norm[v] = 1.0f / sqrtf((float)(d > 0 ? d : 1));
        if (v == NN-1) g_rowptr[NN] = ex + d;
    }
}

__global__ void k_fill(const int* __restrict__ src, const int* __restrict__ dst) {
    int e = blockIdx.x*blockDim.x + threadIdx.x;
    if (e < NE) {
        int p = atomicAdd(&g_cursor[dst[e]], 1);
        g_colidx[p] = src[e];
    }
}

__global__ void k_zero2() {
    int g = blockIdx.x*blockDim.x + threadIdx.x;
    if (g < NH4) g_h0[g] = make_uint4(0u, 0u, 0u, 0u);
    if (g < NC4) g_base[g] = make_float4(0.f, 0.f, 0.f, 0.f);
}

// error[mask] = onehot(y_true) - y_soft[mask]; last occurrence wins (mask sorted)
__global__ void k_scatter1(const float* __restrict__ y_soft,
                           const int* __restrict__ mask,
                           const int* __restrict__ y_true) {
    int g = blockIdx.x*blockDim.x + threadIdx.x;
    if (g >= NT*NC) return;
    int i = g / NC, c = g - NC*i;
    int m = mask[i];
    bool last = (i == NT-1) || (mask[i+1] != m);
    if (last) {
        float err = ((c == y_true[i]) ? 1.0f : 0.0f) - y_soft[m*NC + c];
        ((__half*)g_h0)[m*NC + c]  = __float2half_rn(err * g_norm[m]);  // pre-scaled h
        ((float*)g_base)[m*NC + c] = (1.0f - ALPHA_C) * err;
        ((float*)g_y)[m*NC + c]    = err;                               // raw error for sigma
    }
}

// sigma = sum_i sum_c |error[mask[i]][c]|  (duplicates count repeatedly)
__global__ void k_sigma(const int* __restrict__ mask) {
    __shared__ float sh[256];
    int g = blockIdx.x*256 + threadIdx.x;
    float val = 0.f;
    if (g < NT*NC) {
        int i = g / NC, c = g - NC*i;
        int m = mask[i];
        val = fabsf(((const float*)g_y)[m*NC + c]);
    }
    sh[threadIdx.x] = val;
    __syncthreads();
    for (int o = 128; o; o >>= 1) {
        if (threadIdx.x < o) sh[threadIdx.x] += sh[threadIdx.x + o];
        __syncthreads();
    }
    if (threadIdx.x == 0) atomicAdd(&g_sigma, (double)sh[0]);
}

// one propagation layer (fp16 h): y = clamp(base + alpha*norm_v * sum h_u)
// thread handles 8 classes: g in [0, NN*5), v=g/5, j=g%5
__global__ void k_prop(const uint4* __restrict__ hin,
                       uint4* __restrict__ hout,
                       float4* __restrict__ yout,
                       float alpha, float lo, float hi) {
    int g = blockIdx.x*blockDim.x + threadIdx.x;
    if (g >= NH4) return;
    int v = g / HJ;
    int j = g - v*HJ;
    int s = __ldg(&g_rowptr[v]);
    int e = __ldg(&g_rowptr[v+1]);
    float2 a0 = make_float2(0.f,0.f), a1 = a0, a2 = a0, a3 = a0;
    #pragma unroll 4
    for (int k = s; k < e; k++) {
        int u = __ldg(&g_colidx[k]);
        uint4 t = __ldg(&hin[u*HJ + j]);
        float2 f;
        f = __half22float2(*reinterpret_cast<const __half2*>(&t.x)); a0.x += f.x; a0.y += f.y;
        f = __half22float2(*reinterpret_cast<const __half2*>(&t.y)); a1.x += f.x; a1.y += f.y;
        f = __half22float2(*reinterpret_cast<const __half2*>(&t.z)); a2.x += f.x; a2.y += f.y;
        f = __half22float2(*reinterpret_cast<const __half2*>(&t.w)); a3.x += f.x; a3.y += f.y;
    }
    float nv = __ldg(&g_norm[v]);
    float a = alpha * nv;
    const float4* bp = g_base + v*CJ + j*2;
    float4 b0 = bp[0];
    float4 b1 = bp[1];
    float y0 = fminf(fmaxf(fmaf(a, a0.x, b0.x), lo), hi);
    float y1 = fminf(fmaxf(fmaf(a, a0.y, b0.y), lo), hi);
    float y2 = fminf(fmaxf(fmaf(a, a1.x, b0.z), lo), hi);
    float y3 = fminf(fmaxf(fmaf(a, a1.y, b0.w), lo), hi);
    float y4 = fminf(fmaxf(fmaf(a, a2.x, b1.x), lo), hi);
    float y5 = fminf(fmaxf(fmaf(a, a2.y, b1.y), lo), hi);
    float y6 = fminf(fmaxf(fmaf(a, a3.x, b1.z), lo), hi);
    float y7 = fminf(fmaxf(fmaf(a, a3.y, b1.w), lo), hi);
    if (yout) {
        yout[v*CJ + j*2]     = make_float4(y0, y1, y2, y3);
        yout[v*CJ + j*2 + 1] = make_float4(y4, y5, y6, y7);
    }
    if (hout) {
        __half2 h0 = __floats2half2_rn(y0*nv, y1*nv);
        __half2 h1 = __floats2half2_rn(y2*nv, y3*nv);
        __half2 h2 = __floats2half2_rn(y4*nv, y5*nv);
        __half2 h3 = __floats2half2_rn(y6*nv, y7*nv);
        uint4 o;
        o.x = *reinterpret_cast<unsigned*>(&h0);
        o.y = *reinterpret_cast<unsigned*>(&h1);
        o.z = *reinterpret_cast<unsigned*>(&h2);
        o.w = *reinterpret_cast<unsigned*>(&h3);
        hout[g] = o;
    }
}

__global__ void k_scale() {
    int v = blockIdx.x*blockDim.x + threadIdx.x;
    if (v >= NN) return;
    float denom = 0.f;
    #pragma unroll
    for (int j = 0; j < CJ; j++) {
        float4 t = g_y[v*CJ + j];
        denom += fabsf(t.x) + fabsf(t.y) + fabsf(t.z) + fabsf(t.w);
    }
    float sig = (float)g_sigma / (float)NT;
    float s = sig / denom;
    if (isinf(s) || s > 1000.0f) s = 1.0f;
    g_scalebuf[v] = s;
}

// y1 = y_soft + scale*smoothed_error; emit h = fp16(y1*norm), base = (1-as)*y1
__global__ void k_apply(const float4* __restrict__ y_soft) {
    int g = blockIdx.x*blockDim.x + threadIdx.x;
    if (g >= NC4) return;
    int v = g / CJ;
    float s = g_scalebuf[v];
    float nv = g_norm[v];
    float4 se = g_y[g];
    float4 ys = y_soft[g];
    float4 y1;
    y1.x = fmaf(s, se.x, ys.x);
    y1.y = fmaf(s, se.y, ys.y);
    y1.z = fmaf(s, se.z, ys.z);
    y1.w = fmaf(s, se.w, ys.w);
    __half2 p0 = __floats2half2_rn(y1.x*nv, y1.y*nv);
    __half2 p1 = __floats2half2_rn(y1.z*nv, y1.w*nv);
    uint2 hw;
    hw.x = *reinterpret_cast<unsigned*>(&p0);
    hw.y = *reinterpret_cast<unsigned*>(&p1);
    ((uint2*)g_h0)[g] = hw;
    float4 b;
    const float oma = 1.0f - ALPHA_S;
    b.x = oma*y1.x; b.y = oma*y1.y; b.z = oma*y1.z; b.w = oma*y1.w;
    g_base[g] = b;
}

// y1[mask] = onehot(y_true), last occurrence wins; update h and base rows
__global__ void k_scatter2(const int* __restrict__ mask,
                           const int* __restrict__ y_true) {
    int g = blockIdx.x*blockDim.x + threadIdx.x;
    if (g >= NT*NC) return;
    int i = g / NC, c = g - NC*i;
    int m = mask[i];
    bool last = (i == NT-1) || (mask[i+1] != m);
    if (last) {
        float val = (c == y_true[i]) ? 1.0f : 0.0f;
        ((__half*)g_h0)[m*NC + c]  = __float2half_rn(val * g_norm[m]);
        ((float*)g_base)[m*NC + c] = (1.0f - ALPHA_S) * val;
    }
}

extern "C" void kernel_launch(void* const* d_in, const int* in_sizes, int n_in,
                              void* d_out, int out_size) {
    const float4* y_soft = (const float4*)d_in[0];
    const float*  y_soft_f = (const float*)d_in[0];
    const int* src    = (const int*)d_in[1];
    const int* dst    = (const int*)d_in[2];
    const int* y_true = (const int*)d_in[3];
    const int* mask   = (const int*)d_in[4];

    uint4 *h0, *h1;
    float4 *yb;
    cudaGetSymbolAddress((void**)&h0, g_h0);
    cudaGetSymbolAddress((void**)&h1, g_h1);
    cudaGetSymbolAddress((void**)&yb, g_y);

    const int B = 256;
    const int GN  = (NN + B - 1) / B;
    const int GE  = (NE + B - 1) / B;
    const int G4  = (NC4 + B - 1) / B;
    const int GH  = (NH4 + B - 1) / B;
    const int GTC = (NT*NC + B - 1) / B;

    // ---- build CSR + norm ----
    k_init<<<GN, B>>>();
    k_count<<<GE, B>>>(dst);
    k_scan1<<<SCAN_B, SCAN_T>>>();
    k_scan2<<<1, 32>>>();
    k_scan3<<<SCAN_B, SCAN_T>>>();
    k_fill<<<GE, B>>>(src, dst);

    // ---- correct phase ----
    k_zero2<<<G4, B>>>();
    k_scatter1<<<GTC, B>>>(y_soft_f, mask, y_true);
    k_sigma<<<GTC, B>>>(mask);
    for (int i = 0; i < 9; i++)
        k_prop<<<GH, B>>>((i & 1) ? h1 : h0, (i & 1) ? h0 : h1, nullptr,
                          ALPHA_C, -1.0f, 1.0f);
    k_prop<<<GH, B>>>(h1, nullptr, yb, ALPHA_C, -1.0f, 1.0f);  // smoothed_error -> g_y

    // ---- scale + apply + re-mask ----
    k_scale<<<GN, B>>>();
    k_apply<<<G4, B>>>(y_soft);
    k_scatter2<<<GTC, B>>>(mask, y_true);

    // ---- smooth phase ----
    for (int i = 0; i < 9; i++)
        k_prop<<<GH, B>>>((i & 1) ? h1 : h0, (i & 1) ? h0 : h1, nullptr,
                          ALPHA_S, 0.0f, 1.0f);
    k_prop<<<GH, B>>>(h1, nullptr, (float4*)d_out, ALPHA_S, 0.0f, 1.0f);
}

// round 6
// speedup vs baseline: 1.2650x; 1.0349x over previous
#include <cuda_runtime.h>
#include <cuda_fp16.h>
#include <math.h>

#define NN 100000
#define NE 1600000
#define NC 40
#define CJ 10              // 40 floats = 10 float4 chunks (fp32 buffers)
#define HJ 5               // 40 halves = 5 uint4 chunks (fp16 buffers)
#define NT 50000
#define NC4 (NN*CJ)
#define NH4 (NN*HJ)
#define SCAN_T 1024
#define SCAN_B ((NN + SCAN_T - 1)/SCAN_T)

#define ALPHA_C 0.979f
#define ALPHA_S 0.756f

// ---- scratch (static device globals: allocation-free) ----
static __device__ int    g_deg[NN];
static __device__ int    g_rowptr[NN+1];
static __device__ int    g_cursor[NN];
static __device__ int    g_colidx[NE];
static __device__ float  g_norm[NN];
static __device__ float  g_scalebuf[NN];
static __device__ uint4  g_h0[NH4];     // fp16 feature buffer (ping)
static __device__ uint4  g_h1[NH4];     // fp16 feature buffer (pong)
static __device__ uint4  g_baseh[NH4];  // fp16 (1-alpha)*y0 anchor
static __device__ float4 g_y[NC4];      // smoothed_error (fp32)
static __device__ int    g_bsum[SCAN_B];
static __device__ double g_sigma;

__global__ void k_init() {
    int v = blockIdx.x*blockDim.x + threadIdx.x;
    if (v < NN) g_deg[v] = 0;
    if (v == 0) g_sigma = 0.0;
}

__global__ void k_count(const int* __restrict__ dst) {
    int e = blockIdx.x*blockDim.x + threadIdx.x;
    if (e < NE) atomicAdd(&g_deg[dst[e]], 1);
}

__global__ void k_scan1() {
    __shared__ int sh[32];
    int v = blockIdx.x*SCAN_T + threadIdx.x;
    int d = (v < NN) ? g_deg[v] : 0;
    int s = d;
    #pragma unroll
    for (int o = 16; o; o >>= 1) s += __shfl_down_sync(0xffffffffu, s, o);
    if ((threadIdx.x & 31) == 0) sh[threadIdx.x >> 5] = s;
    __syncthreads();
    if (threadIdx.x < 32) {
        int t = sh[threadIdx.x];
        #pragma unroll
        for (int o = 16; o; o >>= 1) t += __shfl_down_sync(0xffffffffu, t, o);
        if (threadIdx.x == 0) g_bsum[blockIdx.x] = t;
    }
}

// parallel exclusive scan of g_bsum[SCAN_B] (SCAN_B=98 <= 128), one block of 128
__global__ void k_scan2() {
    __shared__ int wsum[4];
    int t = threadIdx.x;
    int lane = t & 31, w = t >> 5;
    int val = (t < SCAN_B) ? g_bsum[t] : 0;
    int inc = val;
    #pragma unroll
    for (int o = 1; o < 32; o <<= 1) {
        int x = __shfl_up_sync(0xffffffffu, inc, o);
        if (lane >= o) inc += x;
    }
    if (lane == 31) wsum[w] = inc;
    __syncthreads();
    if (t == 0) {
        int r = 0;
        #pragma unroll
        for (int i = 0; i < 4; i++) { int x = wsum[i]; wsum[i] = r; r += x; }
    }
    __syncthreads();
    if (t < SCAN_B) g_bsum[t] = inc - val + wsum[w];   // exclusive
}

__global__ void k_scan3() {
    __shared__ int wsum[32];
    int v = blockIdx.x*SCAN_T + threadIdx.x;
    int d = (v < NN) ? g_deg[v] : 0;
    int lane = threadIdx.x & 31, w = threadIdx.x >> 5;
    int inc = d;
    #pragma unroll
    for (int o = 1; o < 32; o <<= 1) {
        int t = __shfl_up_sync(0xffffffffu, inc, o);
        if (lane >= o) inc += t;
    }
    if (lane == 31) wsum[w] = inc;
    __syncthreads();
    if (w == 0) {
        int t = wsum[lane];
        int ti = t;
        #pragma unroll
        for (int o = 1; o < 32; o <<= 1) {
            int x = __shfl_up_sync(0xffffffffu, ti, o);
            if (lane >= o) ti += x;
        }
        wsum[lane] = ti - t;   // exclusive
    }
    __syncthreads();
    int ex = inc - d + wsum[w] + g_bsum[blockIdx.x];
    if (v < NN) {
        g_rowptr[v] = ex;
        g_cursor[v] = ex;
        g_norm[v] = 1.0f / sqrtf((float)(d > 0 ? d : 1));
        if (v == NN-1) g_rowptr[NN] = ex + d;
    }
}

__global__ void k_fill(const int* __restrict__ src, const int* __restrict__ dst) {
    int e = blockIdx.x*blockDim.x + threadIdx.x;
    if (e < NE) {
        int p = atomicAdd(&g_cursor[dst[e]], 1);
        g_colidx[p] = src[e];
    }
}

__global__ void k_zero2() {
    int g = blockIdx.x*blockDim.x + threadIdx.x;
    if (g < NH4) {
        uint4 z = make_uint4(0u,0u,0u,0u);
        g_h0[g] = z;
        g_baseh[g] = z;
    }
}

// error[mask] = onehot(y_true) - y_soft[mask]; last occurrence wins (mask sorted).
// Fused sigma: sigma = sum_i sum_c |error_final[mask[i],c]|; a run of length r
// contributes r * |err_last| per class, computed by the run-last thread.
__global__ void k_scatter1(const float* __restrict__ y_soft,
                           const int* __restrict__ mask,
                           const int* __restrict__ y_true) {
    __shared__ float sh[256];
    int g = blockIdx.x*blockDim.x + threadIdx.x;
    float contrib = 0.f;
    if (g < NT*NC) {
        int i = g / NC, c = g - NC*i;
        int m = mask[i];
        bool last = (i == NT-1) || (mask[i+1] != m);
        if (last) {
            float err = ((c == y_true[i]) ? 1.0f : 0.0f) - y_soft[m*NC + c];
            ((__half*)g_h0)[m*NC + c]    = __float2half_rn(err * g_norm[m]);
            ((__half*)g_baseh)[m*NC + c] = __float2half_rn((1.0f - ALPHA_C) * err);
            int r = 1, k = i;
            while (k > 0 && mask[k-1] == m) { r++; k--; }
            contrib = (float)r * fabsf(err);
        }
    }
    sh[threadIdx.x] = contrib;
    __syncthreads();
    for (int o = 128; o; o >>= 1) {
        if (threadIdx.x < o) sh[threadIdx.x] += sh[threadIdx.x + o];
        __syncthreads();
    }
    if (threadIdx.x == 0 && sh[0] != 0.f) atomicAdd(&g_sigma, (double)sh[0]);
}

// one propagation layer (fp16 h + fp16 base): y = clamp(base + alpha*norm_v * sum h_u)
// thread handles 8 classes: g in [0, NN*5), v=g/5, j=g%5
__global__ void k_prop(const uint4* __restrict__ hin,
                       uint4* __restrict__ hout,
                       float4* __restrict__ yout,
                       float alpha, float lo, float hi) {
    int g = blockIdx.x*blockDim.x + threadIdx.x;
    if (g >= NH4) return;
    int v = g / HJ;
    int j = g - v*HJ;
    int s = __ldg(&g_rowptr[v]);
    int e = __ldg(&g_rowptr[v+1]);
    float2 a0 = make_float2(0.f,0.f), a1 = a0, a2 = a0, a3 = a0;
    #pragma unroll 4
    for (int k = s; k < e; k++) {
        int u = __ldg(&g_colidx[k]);
        uint4 t = __ldg(&hin[u*HJ + j]);
        float2 f;
        f = __half22float2(*reinterpret_cast<const __half2*>(&t.x)); a0.x += f.x; a0.y += f.y;
        f = __half22float2(*reinterpret_cast<const __half2*>(&t.y)); a1.x += f.x; a1.y += f.y;
        f = __half22float2(*reinterpret_cast<const __half2*>(&t.z)); a2.x += f.x; a2.y += f.y;
        f = __half22float2(*reinterpret_cast<const __half2*>(&t.w)); a3.x += f.x; a3.y += f.y;
    }
    float nv = __ldg(&g_norm[v]);
    float a = alpha * nv;
    uint4 bh = __ldg(&g_baseh[g]);
    float2 b0 = __half22float2(*reinterpret_cast<const __half2*>(&bh.x));
    float2 b1 = __half22float2(*reinterpret_cast<const __half2*>(&bh.y));
    float2 b2 = __half22float2(*reinterpret_cast<const __half2*>(&bh.z));
    float2 b3 = __half22float2(*reinterpret_cast<const __half2*>(&bh.w));
    float y0 = fminf(fmaxf(fmaf(a, a0.x, b0.x), lo), hi);
    float y1 = fminf(fmaxf(fmaf(a, a0.y, b0.y), lo), hi);
    float y2 = fminf(fmaxf(fmaf(a, a1.x, b1.x), lo), hi);
    float y3 = fminf(fmaxf(fmaf(a, a1.y, b1.y), lo), hi);
    float y4 = fminf(fmaxf(fmaf(a, a2.x, b2.x), lo), hi);
    float y5 = fminf(fmaxf(fmaf(a, a2.y, b2.y), lo), hi);
    float y6 = fminf(fmaxf(fmaf(a, a3.x, b3.x), lo), hi);
    float y7 = fminf(fmaxf(fmaf(a, a3.y, b3.y), lo), hi);
    if (yout) {
        yout[v*CJ + j*2]     = make_float4(y0, y1, y2, y3);
        yout[v*CJ + j*2 + 1] = make_float4(y4, y5, y6, y7);
    }
    if (hout) {
        __half2 h0 = __floats2half2_rn(y0*nv, y1*nv);
        __half2 h1 = __floats2half2_rn(y2*nv, y3*nv);
        __half2 h2 = __floats2half2_rn(y4*nv, y5*nv);
        __half2 h3 = __floats2half2_rn(y6*nv, y7*nv);
        uint4 o;
        o.x = *reinterpret_cast<unsigned*>(&h0);
        o.y = *reinterpret_cast<unsigned*>(&h1);
        o.z = *reinterpret_cast<unsigned*>(&h2);
        o.w = *reinterpret_cast<unsigned*>(&h3);
        hout[g] = o;
    }
}

__global__ void k_scale() {
    int v = blockIdx.x*blockDim.x + threadIdx.x;
    if (v >= NN) return;
    float denom = 0.f;
    #pragma unroll
    for (int j = 0; j < CJ; j++) {
        float4 t = g_y[v*CJ + j];
        denom += fabsf(t.x) + fabsf(t.y) + fabsf(t.z) + fabsf(t.w);
    }
    float sig = (float)g_sigma / (float)NT;
    float s = sig / denom;
    if (isinf(s) || s > 1000.0f) s = 1.0f;
    g_scalebuf[v] = s;
}

// y1 = y_soft + scale*smoothed_error; emit h = fp16(y1*norm), base = fp16((1-as)*y1)
// g covers 4 classes (CJ layout)
__global__ void k_apply(const float4* __restrict__ y_soft) {
    int g = blockIdx.x*blockDim.x + threadIdx.x;
    if (g >= NC4) return;
    int v = g / CJ;
    float s = g_scalebuf[v];
    float nv = g_norm[v];
    float4 se = g_y[g];
    float4 ys = y_soft[g];
    float4 y1;
    y1.x = fmaf(s, se.x, ys.x);
    y1.y = fmaf(s, se.y, ys.y);
    y1.z = fmaf(s, se.z, ys.z);
    y1.w = fmaf(s, se.w, ys.w);
    __half2 p0 = __floats2half2_rn(y1.x*nv, y1.y*nv);
    __half2 p1 = __floats2half2_rn(y1.z*nv, y1.w*nv);
    uint2 hw;
    hw.x = *reinterpret_cast<unsigned*>(&p0);
    hw.y = *reinterpret_cast<unsigned*>(&p1);
    ((uint2*)g_h0)[g] = hw;
    const float oma = 1.0f - ALPHA_S;
    __half2 q0 = __floats2half2_rn(oma*y1.x, oma*y1.y);
    __half2 q1 = __floats2half2_rn(oma*y1.z, oma*y1.w);
    uint2 bw;
    bw.x = *reinterpret_cast<unsigned*>(&q0);
    bw.y = *reinterpret_cast<unsigned*>(&q1);
    ((uint2*)g_baseh)[g] = bw;
}

// y1[mask] = onehot(y_true), last occurrence wins; update h and base rows
__global__ void k_scatter2(const int* __restrict__ mask,
                           const int* __restrict__ y_true) {
    int g = blockIdx.x*blockDim.x + threadIdx.x;
    if (g >= NT*NC) return;
    int i = g / NC, c = g - NC*i;
    int m = mask[i];
    bool last = (i == NT-1) || (mask[i+1] != m);
    if (last) {
        float val = (c == y_true[i]) ? 1.0f : 0.0f;
        ((__half*)g_h0)[m*NC + c]    = __float2half_rn(val * g_norm[m]);
        ((__half*)g_baseh)[m*NC + c] = __float2half_rn((1.0f - ALPHA_S) * val);
    }
}

extern "C" void kernel_launch(void* const* d_in, const int* in_sizes, int n_in,
                              void* d_out, int out_size) {
    const float4* y_soft = (const float4*)d_in[0];
    const float*  y_soft_f = (const float*)d_in[0];
    const int* src    = (const int*)d_in[1];
    const int* dst    = (const int*)d_in[2];
    const int* y_true = (const int*)d_in[3];
    const int* mask   = (const int*)d_in[4];

    uint4 *h0, *h1;
    float4 *yb;
    cudaGetSymbolAddress((void**)&h0, g_h0);
    cudaGetSymbolAddress((void**)&h1, g_h1);
    cudaGetSymbolAddress((void**)&yb, g_y);

    const int B = 256;
    const int GN  = (NN + B - 1) / B;
    const int GE  = (NE + B - 1) / B;
    const int G4  = (NC4 + B - 1) / B;
    const int GH  = (NH4 + B - 1) / B;
    const int GTC = (NT*NC + B - 1) / B;

    // ---- build CSR + norm ----
    k_init<<<GN, B>>>();
    k_count<<<GE, B>>>(dst);
    k_scan1<<<SCAN_B, SCAN_T>>>();
    k_scan2<<<1, 128>>>();
    k_scan3<<<SCAN_B, SCAN_T>>>();
    k_fill<<<GE, B>>>(src, dst);

    // ---- correct phase ----
    k_zero2<<<GH, B>>>();
    k_scatter1<<<GTC, B>>>(y_soft_f, mask, y_true);
    for (int i = 0; i < 9; i++)
        k_prop<<<GH, B>>>((i & 1) ? h1 : h0, (i & 1) ? h0 : h1, nullptr,
                          ALPHA_C, -1.0f, 1.0f);
    k_prop<<<GH, B>>>(h1, nullptr, yb, ALPHA_C, -1.0f, 1.0f);  // smoothed_error -> g_y

    // ---- scale + apply + re-mask ----
    k_scale<<<GN, B>>>();
    k_apply<<<G4, B>>>(y_soft);
    k_scatter2<<<GTC, B>>>(mask, y_true);

    // ---- smooth phase ----
    for (int i = 0; i < 9; i++)
        k_prop<<<GH, B>>>((i & 1) ? h1 : h0, (i & 1) ? h0 : h1, nullptr,
                          ALPHA_S, 0.0f, 1.0f);
    k_prop<<<GH, B>>>(h1, nullptr, (float4*)d_out, ALPHA_S, 0.0f, 1.0f);
}